// round 3
// baseline (speedup 1.0000x reference)
#include <cuda_runtime.h>
#include <cuda_bf16.h>
#include <stdint.h>

// Problem constants
#define N_ROWS 16384
#define F_DIM  256
#define K_SEL  8192   // ceil(0.5 * 16384)
#define NBINS  16384  // top-14-bit buckets of the u64 sort key

// Output layout (flat f32): X_pooled [K_SEL*F_DIM] | A_pooled [K_SEL*K_SEL] | idx [K_SEL]
#define OUT_X_OFF 0
#define OUT_A_OFF (K_SEL * F_DIM)                       // 2,097,152
#define OUT_I_OFF (OUT_A_OFF + (size_t)K_SEL * K_SEL)   // 69,206,016

// Scratch (device globals: no allocations allowed)
__device__ unsigned long long g_keys[N_ROWS];    // per-row sort key
__device__ unsigned long long g_bkeys[N_ROWS];   // keys grouped by bucket
__device__ int g_hist[NBINS];
__device__ int g_base[NBINS + 1];                // exclusive prefix + sentinel
__device__ int g_cursor[NBINS];                  // atomic scatter cursors
__device__ int g_idx[K_SEL];

// ---------------------------------------------------------------------------
// Kernel 0: zero the histogram.
// ---------------------------------------------------------------------------
__global__ __launch_bounds__(1024) void zero_hist_kernel()
{
    g_hist[blockIdx.x * 1024 + threadIdx.x] = 0;
}

// ---------------------------------------------------------------------------
// Kernel 1: scores = X @ v ; build sortable u64 key; histogram top 14 bits.
// One warp per row, lane-strided accumulation with EXPLICIT rounded mul+add
// (NO fma) to bit-match XLA's fused mul+row-reduce, then xor shuffle tree.
// key = (~orderedU32(score) << 32) | row : ascending key == descending score,
// ties broken by ascending row index (lax.top_k semantics). DO NOT TOUCH MATH.
// ---------------------------------------------------------------------------
__global__ __launch_bounds__(256) void scores_kernel(
    const float* __restrict__ X, const float* __restrict__ sv)
{
    int gwarp = (blockIdx.x * blockDim.x + threadIdx.x) >> 5;
    int lane  = threadIdx.x & 31;
    if (gwarp >= N_ROWS) return;

    const float* xr = X + (size_t)gwarp * F_DIM;
    float acc = 0.0f;
#pragma unroll
    for (int t = 0; t < F_DIM / 32; t++) {
        int c = lane + 32 * t;
        acc = __fadd_rn(acc, __fmul_rn(__ldg(xr + c), __ldg(sv + c)));
    }
#pragma unroll
    for (int o = 16; o > 0; o >>= 1)
        acc = __fadd_rn(acc, __shfl_xor_sync(0xFFFFFFFFu, acc, o));

    if (lane == 0) {
        unsigned ub = __float_as_uint(acc);
        unsigned u = (ub & 0x80000000u) ? ~ub : (ub | 0x80000000u);
        unsigned long long key =
            ((unsigned long long)(~u) << 32) | (unsigned)gwarp;
        g_keys[gwarp] = key;
        atomicAdd(&g_hist[(int)(key >> 50)], 1);
    }
}

// ---------------------------------------------------------------------------
// Kernel 2: exclusive prefix over 16384 bins (single block, 256 threads,
// 64 bins/thread; thread-0 serial scan of the 256 partials).
// ---------------------------------------------------------------------------
__global__ __launch_bounds__(256) void scan_kernel()
{
    __shared__ int part[256];
    __shared__ int partpref[256];
    int t = threadIdx.x;

    int s = 0;
#pragma unroll
    for (int j = 0; j < 64; j++) s += g_hist[t * 64 + j];
    part[t] = s;
    __syncthreads();

    if (t == 0) {
        int acc = 0;
        for (int j = 0; j < 256; j++) { partpref[j] = acc; acc += part[j]; }
    }
    __syncthreads();

    int acc = partpref[t];
#pragma unroll
    for (int j = 0; j < 64; j++) {
        int b = t * 64 + j;
        g_base[b] = acc;
        g_cursor[b] = acc;
        acc += g_hist[b];
    }
    if (t == 255) g_base[NBINS] = N_ROWS;
}

// ---------------------------------------------------------------------------
// Kernel 3: scatter keys into bucket-grouped order (intra-bucket order is
// atomic-arrival order — harmless: ranking below uses full unique keys).
// ---------------------------------------------------------------------------
__global__ __launch_bounds__(256) void bucket_scatter_kernel()
{
    int i = blockIdx.x * 256 + threadIdx.x;
    unsigned long long key = g_keys[i];
    int b = (int)(key >> 50);
    int pos = atomicAdd(&g_cursor[b], 1);
    g_bkeys[pos] = key;
}

// ---------------------------------------------------------------------------
// Kernel 4: exact global rank = bucket_base + strict-less count within the
// bucket (keys unique -> permutation). rank < K_SEL => emit into idx slots.
// ---------------------------------------------------------------------------
__global__ __launch_bounds__(256) void rank_emit_kernel(float* __restrict__ out_idx)
{
    int i = blockIdx.x * 256 + threadIdx.x;
    unsigned long long key = g_bkeys[i];
    int b = (int)(key >> 50);
    int lo = g_base[b];
    int hi = g_base[b + 1];

    int r = lo;
    for (int j = lo; j < hi; j++)
        r += (__ldg(&g_bkeys[j]) < key);

    if (r < K_SEL) {
        int row = (int)(unsigned)(key & 0xFFFFFFFFull);
        g_idx[r] = row;
        out_idx[r] = (float)row;
    }
}

// ---------------------------------------------------------------------------
// Kernel 5: X_pooled[p] = X[idx[p]] — flat float4 copy, 1 float4/thread.
// ---------------------------------------------------------------------------
__global__ __launch_bounds__(256) void xgather_kernel(
    const float* __restrict__ X, float* __restrict__ outX)
{
    int gid = blockIdx.x * 256 + threadIdx.x;     // 0 .. 524287
    int p = gid >> 6;                              // row of X_pooled
    int c = gid & 63;                              // float4 column
    int src = g_idx[p];
    ((float4*)outX)[gid] =
        ((const float4*)(X + (size_t)src * F_DIM))[c];
}

// ---------------------------------------------------------------------------
// Kernel 6: A_pooled[p][q] = A[idx[p]][idx[q]].
// One block per output row: stage the full 64KB A-row coalesced into smem,
// gather columns from smem (random LDS), write STG.128 coalesced.
// ---------------------------------------------------------------------------
__global__ __launch_bounds__(256) void agather_kernel(
    const float* __restrict__ A, float* __restrict__ outA)
{
    extern __shared__ float srow[];  // 16384 floats = 64KB
    int p = blockIdx.x;
    int row = g_idx[p];

    const float4* src = (const float4*)(A + (size_t)row * N_ROWS);
    float4* sr4 = (float4*)srow;
#pragma unroll
    for (int t = 0; t < 16; t++)
        sr4[threadIdx.x + 256 * t] = src[threadIdx.x + 256 * t];
    __syncthreads();

    float4* dst = (float4*)(outA + (size_t)p * K_SEL);
    const int4* idx4 = (const int4*)g_idx;
#pragma unroll
    for (int t = 0; t < 8; t++) {
        int q4 = threadIdx.x + 256 * t;      // quad index, coalesced
        int4 id = __ldg(idx4 + q4);
        float4 v;
        v.x = srow[id.x];
        v.y = srow[id.y];
        v.z = srow[id.z];
        v.w = srow[id.w];
        dst[q4] = v;
    }
}

// ---------------------------------------------------------------------------
extern "C" void kernel_launch(void* const* d_in, const int* in_sizes, int n_in,
                              void* d_out, int out_size)
{
    const float* X  = (const float*)d_in[0];   // [16384, 256]
    const float* A  = (const float*)d_in[1];   // [16384, 16384]
    const float* sv = (const float*)d_in[2];   // [256, 1]
    float* out = (float*)d_out;

    cudaFuncSetAttribute(agather_kernel,
                         cudaFuncAttributeMaxDynamicSharedMemorySize, 65536);

    // 0) zero histogram
    zero_hist_kernel<<<NBINS / 1024, 1024>>>();

    // 1) scores + keys + bucket histogram
    scores_kernel<<<(N_ROWS * 32) / 256, 256>>>(X, sv);

    // 2) bucket offsets (exclusive scan)
    scan_kernel<<<1, 256>>>();

    // 3) group keys by bucket
    bucket_scatter_kernel<<<N_ROWS / 256, 256>>>();

    // 4) exact rank within bucket + emit idx (+ idx output tail)
    rank_emit_kernel<<<N_ROWS / 256, 256>>>(out + OUT_I_OFF);

    // 5) X gather
    xgather_kernel<<<(K_SEL * F_DIM / 4) / 256, 256>>>(X, out + OUT_X_OFF);

    // 6) A double-gather (the heavy one)
    agather_kernel<<<K_SEL, 256, 65536>>>(A, out + OUT_A_OFF);
}

// round 4
// speedup vs baseline: 1.0052x; 1.0052x over previous
#include <cuda_runtime.h>
#include <cuda_bf16.h>
#include <stdint.h>

// Problem constants
#define N_ROWS 16384
#define F_DIM  256
#define K_SEL  8192   // ceil(0.5 * 16384)
#define NBINS  16384  // top-14-bit buckets of the u64 sort key

#define SEL_BLOCKS 64
#define SEL_THREADS 256

// Output layout (flat f32): X_pooled [K_SEL*F_DIM] | A_pooled [K_SEL*K_SEL] | idx [K_SEL]
#define OUT_X_OFF 0
#define OUT_A_OFF (K_SEL * F_DIM)                       // 2,097,152
#define OUT_I_OFF (OUT_A_OFF + (size_t)K_SEL * K_SEL)   // 69,206,016

// Scratch (device globals: no allocations allowed)
__device__ unsigned long long g_keys[N_ROWS];    // per-row sort key
__device__ unsigned long long g_bkeys[N_ROWS];   // keys grouped by bucket
__device__ int g_hist[NBINS];
__device__ int g_base[NBINS];                    // bucket exclusive prefix
__device__ int g_cursor[NBINS];                  // scatter cursors (end after scatter)
__device__ unsigned g_bsum[SEL_BLOCKS];          // per-block bin totals
__device__ int g_idx[K_SEL];

// Monotonic grid barrier ticket. NEVER reset — correctness holds across graph
// replays and ncu kernel replays because the goal is computed per-arrival.
__device__ unsigned long long g_ticket;

__device__ __forceinline__ void grid_sync()
{
    __syncthreads();
    if (threadIdx.x == 0) {
        __threadfence();                               // release my writes
        unsigned long long t = atomicAdd(&g_ticket, 1ull) + 1ull;
        unsigned long long goal =
            ((t + SEL_BLOCKS - 1ull) / SEL_BLOCKS) * SEL_BLOCKS;
        unsigned long long cur;
        do {
            asm volatile("ld.acquire.gpu.u64 %0, [%1];"
                         : "=l"(cur) : "l"(&g_ticket));
        } while (cur < goal);
    }
    __syncthreads();
}

// ---------------------------------------------------------------------------
// Fused selection kernel: 64 blocks x 256 threads, co-resident (persistent).
// Phases (separated by grid_sync):
//   A: zero histogram
//   B: scores = X @ v (bit-exact: rounded mul + rounded add, xor shfl tree),
//      build u64 key = (~orderedU32(score) << 32) | row, histogram top 14 bits
//   C: exclusive scan of 16384 bins (block scan + cross-block prefix)
//   D: scatter keys into bucket-grouped order
//   E: exact rank = bucket_base + strict-less count within bucket; emit idx
// ---------------------------------------------------------------------------
__global__ __launch_bounds__(SEL_THREADS) void select_kernel(
    const float* __restrict__ X, const float* __restrict__ sv,
    float* __restrict__ out_idx)
{
    const int tid  = threadIdx.x;
    const int bid  = blockIdx.x;
    const int lane = tid & 31;
    const int wid  = tid >> 5;
    const int gbin = bid * SEL_THREADS + tid;      // 0..16383, 1 bin/elem per thread

    // ---- Phase A: zero histogram --------------------------------------
    g_hist[gbin] = 0;
    grid_sync();

    // ---- Phase B: scores + keys + histogram ----------------------------
    // One warp per row, 32 rows per warp. DO NOT TOUCH THE MATH: explicit
    // rounded mul+add (no fma) + xor tree bit-matches the XLA reference.
    {
        int gwarp = bid * 8 + wid;                 // 0..511
        for (int it = 0; it < 32; it++) {
            int row = gwarp * 32 + it;
            const float* xr = X + (size_t)row * F_DIM;
            float acc = 0.0f;
#pragma unroll
            for (int t = 0; t < F_DIM / 32; t++) {
                int c = lane + 32 * t;
                acc = __fadd_rn(acc, __fmul_rn(__ldg(xr + c), __ldg(sv + c)));
            }
#pragma unroll
            for (int o = 16; o > 0; o >>= 1)
                acc = __fadd_rn(acc, __shfl_xor_sync(0xFFFFFFFFu, acc, o));

            if (lane == 0) {
                unsigned ub = __float_as_uint(acc);
                unsigned u = (ub & 0x80000000u) ? ~ub : (ub | 0x80000000u);
                unsigned long long key =
                    ((unsigned long long)(~u) << 32) | (unsigned)row;
                g_keys[row] = key;
                atomicAdd(&g_hist[(int)(key >> 50)], 1);
            }
        }
    }
    grid_sync();

    // ---- Phase C: exclusive scan over 16384 bins -----------------------
    __shared__ unsigned wsum[8], wpre[8];
    __shared__ unsigned bpre_sh;
    unsigned excl;
    {
        unsigned v = (unsigned)g_hist[gbin];
        unsigned orig = v;
#pragma unroll
        for (int o = 1; o < 32; o <<= 1) {         // inclusive warp scan
            unsigned n = __shfl_up_sync(0xFFFFFFFFu, v, o);
            if (lane >= o) v += n;
        }
        if (lane == 31) wsum[wid] = v;
        __syncthreads();
        if (wid == 0 && lane < 8) {
            unsigned s = wsum[lane];
#pragma unroll
            for (int o = 1; o < 8; o <<= 1) {
                unsigned n = __shfl_up_sync(0xFFu, s, o);
                if (lane >= o) s += n;
            }
            wpre[lane] = s - wsum[lane];           // exclusive warp prefix
            if (lane == 7) g_bsum[bid] = s;        // block total
        }
        __syncthreads();
        excl = v - orig + wpre[wid];               // exclusive within block
    }
    grid_sync();
    {
        // cross-block prefix: sum of g_bsum[0..bid)
        if (wid == 0) {
            unsigned s1 = (lane < bid) ? g_bsum[lane] : 0u;
            unsigned s2 = (32 + lane < bid) ? g_bsum[32 + lane] : 0u;
            unsigned s = s1 + s2;
#pragma unroll
            for (int o = 16; o > 0; o >>= 1)
                s += __shfl_xor_sync(0xFFFFFFFFu, s, o);
            if (lane == 0) bpre_sh = s;
        }
        __syncthreads();
        int base = (int)(bpre_sh + excl);
        g_base[gbin] = base;
        g_cursor[gbin] = base;
    }
    grid_sync();

    // ---- Phase D: bucket-grouped scatter --------------------------------
    // Intra-bucket order is atomic-arrival order — harmless: ranking uses
    // full unique keys, so the final rank is deterministic.
    {
        unsigned long long key = g_keys[gbin];
        int b = (int)(key >> 50);
        int pos = atomicAdd(&g_cursor[b], 1);
        g_bkeys[pos] = key;
    }
    grid_sync();

    // ---- Phase E: exact rank + emit -------------------------------------
    {
        unsigned long long key = g_bkeys[gbin];
        int b = (int)(key >> 50);
        int lo = g_base[b];
        int hi = g_cursor[b];                      // == end of bucket b

        int r = lo;
        int j = lo;
        for (; j + 4 <= hi; j += 4) {
            unsigned long long k0 = __ldg(&g_bkeys[j]);
            unsigned long long k1 = __ldg(&g_bkeys[j + 1]);
            unsigned long long k2 = __ldg(&g_bkeys[j + 2]);
            unsigned long long k3 = __ldg(&g_bkeys[j + 3]);
            r += (k0 < key) + (k1 < key) + (k2 < key) + (k3 < key);
        }
        for (; j < hi; j++)
            r += (__ldg(&g_bkeys[j]) < key);

        if (r < K_SEL) {
            int row = (int)(unsigned)(key & 0xFFFFFFFFull);
            g_idx[r] = row;
            out_idx[r] = (float)row;
        }
    }
}

// ---------------------------------------------------------------------------
// X_pooled[p] = X[idx[p]] — flat float4 copy, 1 float4/thread.
// ---------------------------------------------------------------------------
__global__ __launch_bounds__(256) void xgather_kernel(
    const float* __restrict__ X, float* __restrict__ outX)
{
    int gid = blockIdx.x * 256 + threadIdx.x;     // 0 .. 524287
    int p = gid >> 6;                              // row of X_pooled
    int c = gid & 63;                              // float4 column
    int src = g_idx[p];
    ((float4*)outX)[gid] =
        ((const float4*)(X + (size_t)src * F_DIM))[c];
}

// ---------------------------------------------------------------------------
// A_pooled[p][q] = A[idx[p]][idx[q]].
// One block per output row: stage the full 64KB A-row coalesced into smem,
// gather columns from smem (random LDS), write STG.128 coalesced.
// ---------------------------------------------------------------------------
__global__ __launch_bounds__(256) void agather_kernel(
    const float* __restrict__ A, float* __restrict__ outA)
{
    extern __shared__ float srow[];  // 16384 floats = 64KB
    int p = blockIdx.x;
    int row = g_idx[p];

    const float4* src = (const float4*)(A + (size_t)row * N_ROWS);
    float4* sr4 = (float4*)srow;
#pragma unroll
    for (int t = 0; t < 16; t++)
        sr4[threadIdx.x + 256 * t] = src[threadIdx.x + 256 * t];
    __syncthreads();

    float4* dst = (float4*)(outA + (size_t)p * K_SEL);
    const int4* idx4 = (const int4*)g_idx;
#pragma unroll
    for (int t = 0; t < 8; t++) {
        int q4 = threadIdx.x + 256 * t;      // quad index, coalesced
        int4 id = __ldg(idx4 + q4);
        float4 v;
        v.x = srow[id.x];
        v.y = srow[id.y];
        v.z = srow[id.z];
        v.w = srow[id.w];
        dst[q4] = v;
    }
}

// ---------------------------------------------------------------------------
extern "C" void kernel_launch(void* const* d_in, const int* in_sizes, int n_in,
                              void* d_out, int out_size)
{
    const float* X  = (const float*)d_in[0];   // [16384, 256]
    const float* A  = (const float*)d_in[1];   // [16384, 16384]
    const float* sv = (const float*)d_in[2];   // [256, 1]
    float* out = (float*)d_out;

    cudaFuncSetAttribute(agather_kernel,
                         cudaFuncAttributeMaxDynamicSharedMemorySize, 65536);

    // 1) fused: scores + keys + hist + scan + bucket scatter + rank + idx
    select_kernel<<<SEL_BLOCKS, SEL_THREADS>>>(X, sv, out + OUT_I_OFF);

    // 2) X gather
    xgather_kernel<<<(K_SEL * F_DIM / 4) / 256, 256>>>(X, out + OUT_X_OFF);

    // 3) A double-gather (the heavy one)
    agather_kernel<<<K_SEL, 256, 65536>>>(A, out + OUT_A_OFF);
}

// round 5
// speedup vs baseline: 1.2543x; 1.2478x over previous
#include <cuda_runtime.h>
#include <cuda_bf16.h>
#include <stdint.h>

// Problem constants
#define N_ROWS 16384
#define F_DIM  256
#define K_SEL  8192   // ceil(0.5 * 16384)
#define NBINS  16384  // top-14-bit buckets of the u64 sort key

#define FIN_BLOCKS 64
#define FIN_THREADS 256

// Output layout (flat f32): X_pooled [K_SEL*F_DIM] | A_pooled [K_SEL*K_SEL] | idx [K_SEL]
#define OUT_X_OFF 0
#define OUT_A_OFF (K_SEL * F_DIM)                       // 2,097,152
#define OUT_I_OFF (OUT_A_OFF + (size_t)K_SEL * K_SEL)   // 69,206,016

// Scratch (device globals: no allocations allowed)
__device__ unsigned long long g_keys[N_ROWS];    // per-row sort key
__device__ unsigned long long g_bkeys[N_ROWS];   // keys grouped by bucket
__device__ int g_hist[NBINS];
__device__ int g_base[NBINS];                    // bucket exclusive prefix
__device__ int g_cursor[NBINS];                  // scatter cursors (end after scatter)
__device__ unsigned g_bsum[FIN_BLOCKS];          // per-block bin totals
__device__ int g_idx[K_SEL];

// Monotonic grid barrier ticket. NEVER reset — correct across graph replays
// and ncu kernel replays because the goal is computed per-arrival.
__device__ unsigned long long g_ticket;

__device__ __forceinline__ void grid_sync()
{
    __syncthreads();
    if (threadIdx.x == 0) {
        __threadfence();                               // release my writes
        unsigned long long t = atomicAdd(&g_ticket, 1ull) + 1ull;
        unsigned long long goal =
            ((t + FIN_BLOCKS - 1ull) / FIN_BLOCKS) * FIN_BLOCKS;
        unsigned long long cur;
        do {
            asm volatile("ld.acquire.gpu.u64 %0, [%1];"
                         : "=l"(cur) : "l"(&g_ticket));
        } while (cur < goal);
    }
    __syncthreads();
}

// ---------------------------------------------------------------------------
// Kernel 1 (WIDE): scores = X @ v ; build sortable u64 key; histogram top 14
// bits. One warp per row, 2048 blocks — full-chip memory parallelism.
// EXPLICIT rounded mul + rounded add (NO fma) + xor shuffle tree bit-matches
// the XLA reference reduction. key = (~orderedU32(score) << 32) | row :
// ascending key == descending score, ties -> ascending row (lax.top_k).
// DO NOT TOUCH THE MATH.
// ---------------------------------------------------------------------------
__global__ __launch_bounds__(256) void scores_kernel(
    const float* __restrict__ X, const float* __restrict__ sv)
{
    int gwarp = (blockIdx.x * blockDim.x + threadIdx.x) >> 5;
    int lane  = threadIdx.x & 31;
    if (gwarp >= N_ROWS) return;

    const float* xr = X + (size_t)gwarp * F_DIM;
    float acc = 0.0f;
#pragma unroll
    for (int t = 0; t < F_DIM / 32; t++) {
        int c = lane + 32 * t;
        acc = __fadd_rn(acc, __fmul_rn(__ldg(xr + c), __ldg(sv + c)));
    }
#pragma unroll
    for (int o = 16; o > 0; o >>= 1)
        acc = __fadd_rn(acc, __shfl_xor_sync(0xFFFFFFFFu, acc, o));

    if (lane == 0) {
        unsigned ub = __float_as_uint(acc);
        unsigned u = (ub & 0x80000000u) ? ~ub : (ub | 0x80000000u);
        unsigned long long key =
            ((unsigned long long)(~u) << 32) | (unsigned)gwarp;
        g_keys[gwarp] = key;
        atomicAdd(&g_hist[(int)(key >> 50)], 1);
    }
}

// ---------------------------------------------------------------------------
// Kernel 2 (PERSISTENT, tiny phases): 64 blocks x 256 threads, co-resident.
//   C: exclusive scan of 16384 bins (warp scans + cross-block prefix)
//   D: scatter keys into bucket-grouped order
//   E: exact rank = bucket_base + strict-less count within bucket; emit idx
// Intra-bucket scatter order is atomic-arrival order — harmless: ranking
// compares full unique keys, so the result is deterministic.
// ---------------------------------------------------------------------------
__global__ __launch_bounds__(FIN_THREADS) void finish_kernel(
    float* __restrict__ out_idx)
{
    const int tid  = threadIdx.x;
    const int bid  = blockIdx.x;
    const int lane = tid & 31;
    const int wid  = tid >> 5;
    const int gbin = bid * FIN_THREADS + tid;      // 0..16383

    // ---- Phase C: exclusive scan over 16384 bins -----------------------
    __shared__ unsigned wsum[8], wpre[8];
    __shared__ unsigned bpre_sh;
    unsigned excl;
    {
        unsigned v = (unsigned)g_hist[gbin];
        unsigned orig = v;
#pragma unroll
        for (int o = 1; o < 32; o <<= 1) {         // inclusive warp scan
            unsigned n = __shfl_up_sync(0xFFFFFFFFu, v, o);
            if (lane >= o) v += n;
        }
        if (lane == 31) wsum[wid] = v;
        __syncthreads();
        if (wid == 0 && lane < 8) {
            unsigned s = wsum[lane];
#pragma unroll
            for (int o = 1; o < 8; o <<= 1) {
                unsigned n = __shfl_up_sync(0xFFu, s, o);
                if (lane >= o) s += n;
            }
            wpre[lane] = s - wsum[lane];           // exclusive warp prefix
            if (lane == 7) g_bsum[bid] = s;        // block total
        }
        __syncthreads();
        excl = v - orig + wpre[wid];               // exclusive within block
    }
    grid_sync();
    {
        // cross-block prefix: sum of g_bsum[0..bid)
        if (wid == 0) {
            unsigned s1 = (lane < bid) ? g_bsum[lane] : 0u;
            unsigned s2 = (32 + lane < bid) ? g_bsum[32 + lane] : 0u;
            unsigned s = s1 + s2;
#pragma unroll
            for (int o = 16; o > 0; o >>= 1)
                s += __shfl_xor_sync(0xFFFFFFFFu, s, o);
            if (lane == 0) bpre_sh = s;
        }
        __syncthreads();
        int base = (int)(bpre_sh + excl);
        g_base[gbin] = base;
        g_cursor[gbin] = base;
    }
    grid_sync();

    // ---- Phase D: bucket-grouped scatter --------------------------------
    {
        unsigned long long key = g_keys[gbin];
        int b = (int)(key >> 50);
        int pos = atomicAdd(&g_cursor[b], 1);
        g_bkeys[pos] = key;
    }
    grid_sync();

    // ---- Phase E: exact rank + emit -------------------------------------
    {
        unsigned long long key = g_bkeys[gbin];
        int b = (int)(key >> 50);
        int lo = g_base[b];
        int hi = g_cursor[b];                      // == end of bucket b

        int r = lo;
        int j = lo;
        for (; j + 4 <= hi; j += 4) {
            unsigned long long k0 = __ldg(&g_bkeys[j]);
            unsigned long long k1 = __ldg(&g_bkeys[j + 1]);
            unsigned long long k2 = __ldg(&g_bkeys[j + 2]);
            unsigned long long k3 = __ldg(&g_bkeys[j + 3]);
            r += (k0 < key) + (k1 < key) + (k2 < key) + (k3 < key);
        }
        for (; j < hi; j++)
            r += (__ldg(&g_bkeys[j]) < key);

        if (r < K_SEL) {
            int row = (int)(unsigned)(key & 0xFFFFFFFFull);
            g_idx[r] = row;
            out_idx[r] = (float)row;
        }
    }
}

// ---------------------------------------------------------------------------
// X_pooled[p] = X[idx[p]] — flat float4 copy, 1 float4/thread.
// ---------------------------------------------------------------------------
__global__ __launch_bounds__(256) void xgather_kernel(
    const float* __restrict__ X, float* __restrict__ outX)
{
    int gid = blockIdx.x * 256 + threadIdx.x;     // 0 .. 524287
    int p = gid >> 6;                              // row of X_pooled
    int c = gid & 63;                              // float4 column
    int src = g_idx[p];
    ((float4*)outX)[gid] =
        ((const float4*)(X + (size_t)src * F_DIM))[c];
}

// ---------------------------------------------------------------------------
// A_pooled[p][q] = A[idx[p]][idx[q]].
// One block per output row: stage the full 64KB A-row coalesced into smem,
// gather columns from smem (random LDS), write STG.128 coalesced.
// ---------------------------------------------------------------------------
__global__ __launch_bounds__(256) void agather_kernel(
    const float* __restrict__ A, float* __restrict__ outA)
{
    extern __shared__ float srow[];  // 16384 floats = 64KB
    int p = blockIdx.x;
    int row = g_idx[p];

    const float4* src = (const float4*)(A + (size_t)row * N_ROWS);
    float4* sr4 = (float4*)srow;
#pragma unroll
    for (int t = 0; t < 16; t++)
        sr4[threadIdx.x + 256 * t] = src[threadIdx.x + 256 * t];
    __syncthreads();

    float4* dst = (float4*)(outA + (size_t)p * K_SEL);
    const int4* idx4 = (const int4*)g_idx;
#pragma unroll
    for (int t = 0; t < 8; t++) {
        int q4 = threadIdx.x + 256 * t;      // quad index, coalesced
        int4 id = __ldg(idx4 + q4);
        float4 v;
        v.x = srow[id.x];
        v.y = srow[id.y];
        v.z = srow[id.z];
        v.w = srow[id.w];
        dst[q4] = v;
    }
}

// ---------------------------------------------------------------------------
extern "C" void kernel_launch(void* const* d_in, const int* in_sizes, int n_in,
                              void* d_out, int out_size)
{
    const float* X  = (const float*)d_in[0];   // [16384, 256]
    const float* A  = (const float*)d_in[1];   // [16384, 16384]
    const float* sv = (const float*)d_in[2];   // [256, 1]
    float* out = (float*)d_out;

    cudaFuncSetAttribute(agather_kernel,
                         cudaFuncAttributeMaxDynamicSharedMemorySize, 65536);

    // 0) zero histogram (graph-capturable, no allocation)
    void* hist_ptr = nullptr;
    cudaGetSymbolAddress(&hist_ptr, g_hist);
    cudaMemsetAsync(hist_ptr, 0, NBINS * sizeof(int));

    // 1) scores + keys + bucket histogram (WIDE: full-chip bandwidth)
    scores_kernel<<<(N_ROWS * 32) / 256, 256>>>(X, sv);

    // 2) scan + bucket scatter + rank + emit (persistent, latency-optimized)
    finish_kernel<<<FIN_BLOCKS, FIN_THREADS>>>(out + OUT_I_OFF);

    // 3) X gather
    xgather_kernel<<<(K_SEL * F_DIM / 4) / 256, 256>>>(X, out + OUT_X_OFF);

    // 4) A double-gather (the heavy one)
    agather_kernel<<<K_SEL, 256, 65536>>>(A, out + OUT_A_OFF);
}

// round 6
// speedup vs baseline: 1.3809x; 1.1010x over previous
#include <cuda_runtime.h>
#include <cuda_bf16.h>
#include <stdint.h>

// Problem constants
#define N_ROWS 16384
#define F_DIM  256
#define K_SEL  8192   // ceil(0.5 * 16384)
#define NBINS  16384  // top-14-bit buckets of the u64 sort key

#define FIN_BLOCKS 64
#define FIN_THREADS 256

// Output layout (flat f32): X_pooled [K_SEL*F_DIM] | A_pooled [K_SEL*K_SEL] | idx [K_SEL]
#define OUT_X_OFF 0
#define OUT_A_OFF (K_SEL * F_DIM)                       // 2,097,152
#define OUT_I_OFF (OUT_A_OFF + (size_t)K_SEL * K_SEL)   // 69,206,016

// Scratch (device globals: no allocations allowed).
// NOTE: g_hist relies on zero-initialization at module load; finish_kernel
// re-zeros it after reading so every launch leaves it zeroed (replay-safe).
__device__ unsigned long long g_keys[N_ROWS];    // per-row sort key
__device__ unsigned long long g_bkeys[N_ROWS];   // keys grouped by bucket
__device__ int g_hist[NBINS];
__device__ int g_base[NBINS];                    // bucket exclusive prefix
__device__ int g_cursor[NBINS];                  // scatter cursors (end after scatter)
__device__ unsigned g_bsum[FIN_BLOCKS];          // per-block bin totals
__device__ int g_idx[K_SEL];

// Monotonic grid barrier ticket. NEVER reset — correct across graph replays
// and ncu kernel replays because the goal is computed per-arrival.
__device__ unsigned long long g_ticket;

__device__ __forceinline__ void grid_sync()
{
    __syncthreads();
    if (threadIdx.x == 0) {
        __threadfence();                               // release my writes
        unsigned long long t = atomicAdd(&g_ticket, 1ull) + 1ull;
        unsigned long long goal =
            ((t + FIN_BLOCKS - 1ull) / FIN_BLOCKS) * FIN_BLOCKS;
        unsigned long long cur;
        do {
            asm volatile("ld.acquire.gpu.u64 %0, [%1];"
                         : "=l"(cur) : "l"(&g_ticket));
        } while (cur < goal);
    }
    __syncthreads();
}

// ---------------------------------------------------------------------------
// Kernel 1 (WIDE): scores = X @ v ; build sortable u64 key; histogram top 14
// bits. One warp per row, 2048 blocks — full-chip memory parallelism.
// EXPLICIT rounded mul + rounded add (NO fma) + xor shuffle tree bit-matches
// the XLA reference reduction. key = (~orderedU32(score) << 32) | row :
// ascending key == descending score, ties -> ascending row (lax.top_k).
// DO NOT TOUCH THE MATH.
// ---------------------------------------------------------------------------
__global__ __launch_bounds__(256) void scores_kernel(
    const float* __restrict__ X, const float* __restrict__ sv)
{
    int gwarp = (blockIdx.x * blockDim.x + threadIdx.x) >> 5;
    int lane  = threadIdx.x & 31;
    if (gwarp >= N_ROWS) return;

    const float* xr = X + (size_t)gwarp * F_DIM;
    float acc = 0.0f;
#pragma unroll
    for (int t = 0; t < F_DIM / 32; t++) {
        int c = lane + 32 * t;
        acc = __fadd_rn(acc, __fmul_rn(__ldg(xr + c), __ldg(sv + c)));
    }
#pragma unroll
    for (int o = 16; o > 0; o >>= 1)
        acc = __fadd_rn(acc, __shfl_xor_sync(0xFFFFFFFFu, acc, o));

    if (lane == 0) {
        unsigned ub = __float_as_uint(acc);
        unsigned u = (ub & 0x80000000u) ? ~ub : (ub | 0x80000000u);
        unsigned long long key =
            ((unsigned long long)(~u) << 32) | (unsigned)gwarp;
        g_keys[gwarp] = key;
        atomicAdd(&g_hist[(int)(key >> 50)], 1);
    }
}

// ---------------------------------------------------------------------------
// Kernel 2 (PERSISTENT, tiny phases): 64 blocks x 256 threads, co-resident.
//   C: exclusive scan of 16384 bins (warp scans + cross-block prefix),
//      then re-zero g_hist for the next launch (replay invariant)
//   D: scatter keys into bucket-grouped order
//   E: exact rank = bucket_base + strict-less count within bucket; emit idx
// Intra-bucket scatter order is atomic-arrival order — harmless: ranking
// compares full unique keys, so the result is deterministic.
// ---------------------------------------------------------------------------
__global__ __launch_bounds__(FIN_THREADS) void finish_kernel(
    float* __restrict__ out_idx)
{
    const int tid  = threadIdx.x;
    const int bid  = blockIdx.x;
    const int lane = tid & 31;
    const int wid  = tid >> 5;
    const int gbin = bid * FIN_THREADS + tid;      // 0..16383

    // ---- Phase C: exclusive scan over 16384 bins -----------------------
    __shared__ unsigned wsum[8], wpre[8];
    __shared__ unsigned bpre_sh;
    unsigned excl;
    {
        unsigned v = (unsigned)g_hist[gbin];
        g_hist[gbin] = 0;                          // re-arm for next launch
        unsigned orig = v;
#pragma unroll
        for (int o = 1; o < 32; o <<= 1) {         // inclusive warp scan
            unsigned n = __shfl_up_sync(0xFFFFFFFFu, v, o);
            if (lane >= o) v += n;
        }
        if (lane == 31) wsum[wid] = v;
        __syncthreads();
        if (wid == 0 && lane < 8) {
            unsigned s = wsum[lane];
#pragma unroll
            for (int o = 1; o < 8; o <<= 1) {
                unsigned n = __shfl_up_sync(0xFFu, s, o);
                if (lane >= o) s += n;
            }
            wpre[lane] = s - wsum[lane];           // exclusive warp prefix
            if (lane == 7) g_bsum[bid] = s;        // block total
        }
        __syncthreads();
        excl = v - orig + wpre[wid];               // exclusive within block
    }
    grid_sync();
    {
        // cross-block prefix: sum of g_bsum[0..bid)
        if (wid == 0) {
            unsigned s1 = (lane < bid) ? g_bsum[lane] : 0u;
            unsigned s2 = (32 + lane < bid) ? g_bsum[32 + lane] : 0u;
            unsigned s = s1 + s2;
#pragma unroll
            for (int o = 16; o > 0; o >>= 1)
                s += __shfl_xor_sync(0xFFFFFFFFu, s, o);
            if (lane == 0) bpre_sh = s;
        }
        __syncthreads();
        int base = (int)(bpre_sh + excl);
        g_base[gbin] = base;
        g_cursor[gbin] = base;
    }
    grid_sync();

    // ---- Phase D: bucket-grouped scatter --------------------------------
    {
        unsigned long long key = g_keys[gbin];
        int b = (int)(key >> 50);
        int pos = atomicAdd(&g_cursor[b], 1);
        g_bkeys[pos] = key;
    }
    grid_sync();

    // ---- Phase E: exact rank + emit -------------------------------------
    {
        unsigned long long key = g_bkeys[gbin];
        int b = (int)(key >> 50);
        int lo = g_base[b];
        int hi = g_cursor[b];                      // == end of bucket b

        int r = lo;
        int j = lo;
        for (; j + 4 <= hi; j += 4) {
            unsigned long long k0 = __ldg(&g_bkeys[j]);
            unsigned long long k1 = __ldg(&g_bkeys[j + 1]);
            unsigned long long k2 = __ldg(&g_bkeys[j + 2]);
            unsigned long long k3 = __ldg(&g_bkeys[j + 3]);
            r += (k0 < key) + (k1 < key) + (k2 < key) + (k3 < key);
        }
        for (; j < hi; j++)
            r += (__ldg(&g_bkeys[j]) < key);

        if (r < K_SEL) {
            int row = (int)(unsigned)(key & 0xFFFFFFFFull);
            g_idx[r] = row;
            out_idx[r] = (float)row;
        }
    }
}

// ---------------------------------------------------------------------------
// A_pooled[p][q] = A[idx[p]][idx[q]]  +  X_pooled[p] = X[idx[p]] (folded in).
// One 1024-thread block per output row (2 blocks/SM @ 64KB smem -> 64 warps):
// stage the full 64KB A-row coalesced into smem, gather columns from smem
// (random LDS), write STG.128 coalesced.
// ---------------------------------------------------------------------------
__global__ __launch_bounds__(1024) void agather_kernel(
    const float* __restrict__ A, float* __restrict__ outA,
    const float* __restrict__ X, float* __restrict__ outX)
{
    extern __shared__ float srow[];  // 16384 floats = 64KB
    int p = blockIdx.x;
    int row = g_idx[p];

    const float4* src = (const float4*)(A + (size_t)row * N_ROWS);
    float4* sr4 = (float4*)srow;
#pragma unroll
    for (int t = 0; t < 4; t++)
        sr4[threadIdx.x + 1024 * t] = src[threadIdx.x + 1024 * t];

    // folded X gather: 64 float4 = one X row
    if (threadIdx.x < F_DIM / 4) {
        ((float4*)(outX + (size_t)p * F_DIM))[threadIdx.x] =
            ((const float4*)(X + (size_t)row * F_DIM))[threadIdx.x];
    }
    __syncthreads();

    float4* dst = (float4*)(outA + (size_t)p * K_SEL);
    const int4* idx4 = (const int4*)g_idx;
#pragma unroll
    for (int t = 0; t < 2; t++) {
        int q4 = threadIdx.x + 1024 * t;     // quad index, coalesced
        int4 id = __ldg(idx4 + q4);
        float4 v;
        v.x = srow[id.x];
        v.y = srow[id.y];
        v.z = srow[id.z];
        v.w = srow[id.w];
        dst[q4] = v;
    }
}

// ---------------------------------------------------------------------------
extern "C" void kernel_launch(void* const* d_in, const int* in_sizes, int n_in,
                              void* d_out, int out_size)
{
    const float* X  = (const float*)d_in[0];   // [16384, 256]
    const float* A  = (const float*)d_in[1];   // [16384, 16384]
    const float* sv = (const float*)d_in[2];   // [256, 1]
    float* out = (float*)d_out;

    cudaFuncSetAttribute(agather_kernel,
                         cudaFuncAttributeMaxDynamicSharedMemorySize, 65536);

    // 1) scores + keys + bucket histogram (WIDE: full-chip bandwidth)
    //    (g_hist arrives zeroed: zero-init at load, re-zeroed by finish_kernel)
    scores_kernel<<<(N_ROWS * 32) / 256, 256>>>(X, sv);

    // 2) scan + bucket scatter + rank + emit idx (persistent, latency-optimized)
    finish_kernel<<<FIN_BLOCKS, FIN_THREADS>>>(out + OUT_I_OFF);

    // 3) A double-gather + folded X gather (the heavy one)
    agather_kernel<<<K_SEL, 1024, 65536>>>(A, out + OUT_A_OFF,
                                           X, out + OUT_X_OFF);
}

// round 7
// speedup vs baseline: 1.3859x; 1.0036x over previous
#include <cuda_runtime.h>
#include <cuda_bf16.h>
#include <stdint.h>

// Problem constants
#define N_ROWS 16384
#define F_DIM  256
#define K_SEL  8192   // ceil(0.5 * 16384)
#define NBINS  16384  // top-14-bit buckets of the u64 sort key

#define FIN_BLOCKS 64
#define FIN_THREADS 256

#define AG_BLOCKS 148        // one persistent block per SM
#define AG_THREADS 1024
#define ROW_BYTES 65536      // one A row: 16384 f32

// Output layout (flat f32): X_pooled [K_SEL*F_DIM] | A_pooled [K_SEL*K_SEL] | idx [K_SEL]
#define OUT_X_OFF 0
#define OUT_A_OFF (K_SEL * F_DIM)                       // 2,097,152
#define OUT_I_OFF (OUT_A_OFF + (size_t)K_SEL * K_SEL)   // 69,206,016

// Scratch (device globals: no allocations allowed).
// NOTE: g_hist relies on zero-initialization at module load; finish_kernel
// re-zeros it after reading so every launch leaves it zeroed (replay-safe).
__device__ unsigned long long g_keys[N_ROWS];    // per-row sort key
__device__ unsigned long long g_bkeys[N_ROWS];   // keys grouped by bucket
__device__ int g_hist[NBINS];
__device__ int g_base[NBINS];                    // bucket exclusive prefix
__device__ int g_cursor[NBINS];                  // scatter cursors (end after scatter)
__device__ unsigned g_bsum[FIN_BLOCKS];          // per-block bin totals
__device__ int g_idx[K_SEL];

// Monotonic grid barrier ticket. NEVER reset — correct across graph replays
// and ncu kernel replays because the goal is computed per-arrival.
__device__ unsigned long long g_ticket;

__device__ __forceinline__ void grid_sync()
{
    __syncthreads();
    if (threadIdx.x == 0) {
        __threadfence();                               // release my writes
        unsigned long long t = atomicAdd(&g_ticket, 1ull) + 1ull;
        unsigned long long goal =
            ((t + FIN_BLOCKS - 1ull) / FIN_BLOCKS) * FIN_BLOCKS;
        unsigned long long cur;
        do {
            asm volatile("ld.acquire.gpu.u64 %0, [%1];"
                         : "=l"(cur) : "l"(&g_ticket));
        } while (cur < goal);
    }
    __syncthreads();
}

// ---------------------------------------------------------------------------
// Kernel 1 (WIDE): scores = X @ v ; build sortable u64 key; histogram top 14
// bits. One warp per row, 2048 blocks — full-chip memory parallelism.
// EXPLICIT rounded mul + rounded add (NO fma) + xor shuffle tree bit-matches
// the XLA reference reduction. key = (~orderedU32(score) << 32) | row :
// ascending key == descending score, ties -> ascending row (lax.top_k).
// DO NOT TOUCH THE MATH.
// ---------------------------------------------------------------------------
__global__ __launch_bounds__(256) void scores_kernel(
    const float* __restrict__ X, const float* __restrict__ sv)
{
    int gwarp = (blockIdx.x * blockDim.x + threadIdx.x) >> 5;
    int lane  = threadIdx.x & 31;
    if (gwarp >= N_ROWS) return;

    const float* xr = X + (size_t)gwarp * F_DIM;
    float acc = 0.0f;
#pragma unroll
    for (int t = 0; t < F_DIM / 32; t++) {
        int c = lane + 32 * t;
        acc = __fadd_rn(acc, __fmul_rn(__ldg(xr + c), __ldg(sv + c)));
    }
#pragma unroll
    for (int o = 16; o > 0; o >>= 1)
        acc = __fadd_rn(acc, __shfl_xor_sync(0xFFFFFFFFu, acc, o));

    if (lane == 0) {
        unsigned ub = __float_as_uint(acc);
        unsigned u = (ub & 0x80000000u) ? ~ub : (ub | 0x80000000u);
        unsigned long long key =
            ((unsigned long long)(~u) << 32) | (unsigned)gwarp;
        g_keys[gwarp] = key;
        atomicAdd(&g_hist[(int)(key >> 50)], 1);
    }
}

// ---------------------------------------------------------------------------
// Kernel 2 (PERSISTENT, tiny phases): 64 blocks x 256 threads, co-resident.
//   C: exclusive scan of 16384 bins (+ re-zero g_hist for next launch)
//   D: scatter keys into bucket-grouped order
//   E: exact rank = bucket_base + strict-less count within bucket; emit idx
// Intra-bucket scatter order is atomic-arrival order — harmless: ranking
// compares full unique keys, so the result is deterministic.
// ---------------------------------------------------------------------------
__global__ __launch_bounds__(FIN_THREADS) void finish_kernel(
    float* __restrict__ out_idx)
{
    const int tid  = threadIdx.x;
    const int bid  = blockIdx.x;
    const int lane = tid & 31;
    const int wid  = tid >> 5;
    const int gbin = bid * FIN_THREADS + tid;      // 0..16383

    // ---- Phase C: exclusive scan over 16384 bins -----------------------
    __shared__ unsigned wsum[8], wpre[8];
    __shared__ unsigned bpre_sh;
    unsigned excl;
    {
        unsigned v = (unsigned)g_hist[gbin];
        g_hist[gbin] = 0;                          // re-arm for next launch
        unsigned orig = v;
#pragma unroll
        for (int o = 1; o < 32; o <<= 1) {         // inclusive warp scan
            unsigned n = __shfl_up_sync(0xFFFFFFFFu, v, o);
            if (lane >= o) v += n;
        }
        if (lane == 31) wsum[wid] = v;
        __syncthreads();
        if (wid == 0 && lane < 8) {
            unsigned s = wsum[lane];
#pragma unroll
            for (int o = 1; o < 8; o <<= 1) {
                unsigned n = __shfl_up_sync(0xFFu, s, o);
                if (lane >= o) s += n;
            }
            wpre[lane] = s - wsum[lane];           // exclusive warp prefix
            if (lane == 7) g_bsum[bid] = s;        // block total
        }
        __syncthreads();
        excl = v - orig + wpre[wid];               // exclusive within block
    }
    grid_sync();
    {
        // cross-block prefix: sum of g_bsum[0..bid)
        if (wid == 0) {
            unsigned s1 = (lane < bid) ? g_bsum[lane] : 0u;
            unsigned s2 = (32 + lane < bid) ? g_bsum[32 + lane] : 0u;
            unsigned s = s1 + s2;
#pragma unroll
            for (int o = 16; o > 0; o >>= 1)
                s += __shfl_xor_sync(0xFFFFFFFFu, s, o);
            if (lane == 0) bpre_sh = s;
        }
        __syncthreads();
        int base = (int)(bpre_sh + excl);
        g_base[gbin] = base;
        g_cursor[gbin] = base;
    }
    grid_sync();

    // ---- Phase D: bucket-grouped scatter --------------------------------
    {
        unsigned long long key = g_keys[gbin];
        int b = (int)(key >> 50);
        int pos = atomicAdd(&g_cursor[b], 1);
        g_bkeys[pos] = key;
    }
    grid_sync();

    // ---- Phase E: exact rank + emit -------------------------------------
    {
        unsigned long long key = g_bkeys[gbin];
        int b = (int)(key >> 50);
        int lo = g_base[b];
        int hi = g_cursor[b];                      // == end of bucket b

        int r = lo;
        int j = lo;
        for (; j + 4 <= hi; j += 4) {
            unsigned long long k0 = __ldg(&g_bkeys[j]);
            unsigned long long k1 = __ldg(&g_bkeys[j + 1]);
            unsigned long long k2 = __ldg(&g_bkeys[j + 2]);
            unsigned long long k3 = __ldg(&g_bkeys[j + 3]);
            r += (k0 < key) + (k1 < key) + (k2 < key) + (k3 < key);
        }
        for (; j < hi; j++)
            r += (__ldg(&g_bkeys[j]) < key);

        if (r < K_SEL) {
            int row = (int)(unsigned)(key & 0xFFFFFFFFull);
            g_idx[r] = row;
            out_idx[r] = (float)row;
        }
    }
}

// ---------------------------------------------------------------------------
// Kernel 3 (PERSISTENT, double-buffered TMA): A_pooled[p][q] = A[idx[p]][idx[q]]
// + folded X_pooled[p] = X[idx[p]].
// 148 blocks (1/SM) x 1024 threads. Two 64KB smem row buffers; one producer
// thread prefetches row i+1 via cp.async.bulk (mbarrier complete_tx) while all
// threads gather row i from the other buffer. DRAM reads flow continuously.
// ---------------------------------------------------------------------------
__global__ __launch_bounds__(AG_THREADS) void agather_kernel(
    const float* __restrict__ A, float* __restrict__ outA,
    const float* __restrict__ X, float* __restrict__ outX)
{
    extern __shared__ float sbuf[];                // 2 x 16384 floats (128KB)
    __shared__ unsigned long long mbar[2];

    const int tid = threadIdx.x;
    const int bid = blockIdx.x;

    uint32_t mb0 = (uint32_t)__cvta_generic_to_shared(&mbar[0]);
    uint32_t mb1 = (uint32_t)__cvta_generic_to_shared(&mbar[1]);
    uint32_t sbase = (uint32_t)__cvta_generic_to_shared(sbuf);

    if (tid == 0) {
        asm volatile("mbarrier.init.shared.b64 [%0], 1;" :: "r"(mb0));
        asm volatile("mbarrier.init.shared.b64 [%0], 1;" :: "r"(mb1));
        asm volatile("fence.proxy.async.shared::cta;" ::: "memory");
    }
    __syncthreads();

    const int niters = (K_SEL - bid + AG_BLOCKS - 1) / AG_BLOCKS;

    // prologue: prefetch row for it=0 into buffer 0
    if (tid == 0) {
        int row0 = g_idx[bid];
        const char* src = (const char*)(A + (size_t)row0 * N_ROWS);
        asm volatile("mbarrier.arrive.expect_tx.shared.b64 _, [%0], %1;"
                     :: "r"(mb0), "r"(ROW_BYTES) : "memory");
#pragma unroll
        for (int c = 0; c < 4; c++)
            asm volatile(
                "cp.async.bulk.shared::cluster.global.mbarrier::complete_tx::bytes "
                "[%0], [%1], %2, [%3];"
                :: "r"(sbase + c * 16384), "l"(src + c * 16384),
                   "r"(16384), "r"(mb0) : "memory");
    }

    for (int it = 0; it < niters; it++) {
        const int s = it & 1;
        const int p = bid + it * AG_BLOCKS;

        // prefetch row it+1 into the other buffer (it was fully consumed at
        // the end of iteration it-1 — guaranteed by that iteration's sync).
        const int itn = it + 1;
        if (itn < niters && tid == 0) {
            int nrow = g_idx[bid + itn * AG_BLOCKS];
            const char* src = (const char*)(A + (size_t)nrow * N_ROWS);
            uint32_t dst = sbase + (unsigned)(itn & 1) * ROW_BYTES;
            uint32_t m = (itn & 1) ? mb1 : mb0;
            asm volatile("mbarrier.arrive.expect_tx.shared.b64 _, [%0], %1;"
                         :: "r"(m), "r"(ROW_BYTES) : "memory");
#pragma unroll
            for (int c = 0; c < 4; c++)
                asm volatile(
                    "cp.async.bulk.shared::cluster.global.mbarrier::complete_tx::bytes "
                    "[%0], [%1], %2, [%3];"
                    :: "r"(dst + c * 16384), "l"(src + c * 16384),
                       "r"(16384), "r"(m) : "memory");
        }

        // wait for buffer s (use #k = it>>1, parity k&1)
        {
            uint32_t m = s ? mb1 : mb0;
            unsigned ph = (unsigned)((it >> 1) & 1);
            unsigned done;
            asm volatile(
                "{\n\t.reg .pred p;\n\t"
                "mbarrier.try_wait.parity.acquire.cta.shared::cta.b64 p, [%1], %2;\n\t"
                "selp.b32 %0, 1, 0, p;\n\t}"
                : "=r"(done) : "r"(m), "r"(ph) : "memory");
            while (!done) {
                asm volatile(
                    "{\n\t.reg .pred p;\n\t"
                    "mbarrier.try_wait.parity.acquire.cta.shared::cta.b64 p, [%1], %2, 0x989680;\n\t"
                    "selp.b32 %0, 1, 0, p;\n\t}"
                    : "=r"(done) : "r"(m), "r"(ph) : "memory");
            }
        }

        const float* buf = sbuf + (size_t)s * N_ROWS;
        int row = g_idx[p];

        // folded X gather: 64 float4 = one X row
        if (tid < F_DIM / 4) {
            ((float4*)(outX + (size_t)p * F_DIM))[tid] =
                ((const float4*)(X + (size_t)row * F_DIM))[tid];
        }

        float4* dst = (float4*)(outA + (size_t)p * K_SEL);
        const int4* idx4 = (const int4*)g_idx;
#pragma unroll
        for (int t = 0; t < 2; t++) {
            int q4 = tid + AG_THREADS * t;         // quad index, coalesced
            int4 id = __ldg(idx4 + q4);
            float4 v;
            v.x = buf[id.x];
            v.y = buf[id.y];
            v.z = buf[id.z];
            v.w = buf[id.w];
            dst[q4] = v;
        }

        __syncthreads();   // buffer s fully consumed; safe to overwrite next iter
    }
}

// ---------------------------------------------------------------------------
extern "C" void kernel_launch(void* const* d_in, const int* in_sizes, int n_in,
                              void* d_out, int out_size)
{
    const float* X  = (const float*)d_in[0];   // [16384, 256]
    const float* A  = (const float*)d_in[1];   // [16384, 16384]
    const float* sv = (const float*)d_in[2];   // [256, 1]
    float* out = (float*)d_out;

    cudaFuncSetAttribute(agather_kernel,
                         cudaFuncAttributeMaxDynamicSharedMemorySize,
                         2 * ROW_BYTES);

    // 1) scores + keys + bucket histogram (WIDE: full-chip bandwidth)
    //    (g_hist arrives zeroed: zero-init at load, re-zeroed by finish_kernel)
    scores_kernel<<<(N_ROWS * 32) / 256, 256>>>(X, sv);

    // 2) scan + bucket scatter + rank + emit idx (persistent, latency-optimized)
    finish_kernel<<<FIN_BLOCKS, FIN_THREADS>>>(out + OUT_I_OFF);

    // 3) A double-gather + folded X gather (persistent double-buffered TMA)
    agather_kernel<<<AG_BLOCKS, AG_THREADS, 2 * ROW_BYTES>>>(
        A, out + OUT_A_OFF, X, out + OUT_X_OFF);
}